// round 1
// baseline (speedup 1.0000x reference)
#include <cuda_runtime.h>
#include <math.h>

// Problem constants (fixed by the dataset)
#define NNODES 20000
#define NEDGES 200000
#define NC     32
#define FDIM   13
#define FHID   64
#define NREP   10
#define OUTC   (NC * (NREP + 1))   // 352

// Scratch (allocation-free rule: __device__ globals)
__device__ float g_weights[(size_t)NEDGES * NC * NC];   // 800 MB: per-edge [32x32]
__device__ float g_h1[(size_t)NEDGES * FHID];           // 51 MB
__device__ float g_agg[(size_t)NNODES * NC];            // 2.56 MB
__device__ float g_deg[NNODES];

// ---------------------------------------------------------------------------
// h1 = relu(edge_feats @ fW1 + fb1)   — one warp per edge, lane does k, k+32
// ---------------------------------------------------------------------------
__global__ void h1_kernel(const float* __restrict__ ef,
                          const float* __restrict__ fW1,
                          const float* __restrict__ fb1,
                          int E) {
    int e    = (blockIdx.x * blockDim.x + threadIdx.x) >> 5;
    int lane = threadIdx.x & 31;
    if (e >= E) return;
    float efv = (lane < FDIM) ? ef[(size_t)e * FDIM + lane] : 0.f;
    float a0 = fb1[lane], a1 = fb1[lane + 32];
#pragma unroll
    for (int j = 0; j < FDIM; j++) {
        float x = __shfl_sync(0xffffffffu, efv, j);
        a0 = fmaf(x, fW1[j * FHID + lane],      a0);
        a1 = fmaf(x, fW1[j * FHID + lane + 32], a1);
    }
    g_h1[(size_t)e * FHID + lane]      = fmaxf(a0, 0.f);
    g_h1[(size_t)e * FHID + lane + 32] = fmaxf(a1, 0.f);
}

// ---------------------------------------------------------------------------
// weights = h1 @ fW2 + fb2 : GEMM  M=E, N=1024, K=64.  64x64 tile, 256 thr,
// 4x4 microtile per thread. A stored transposed in smem (As[k][m]).
// ---------------------------------------------------------------------------
__global__ void wgemm_kernel(const float* __restrict__ B,     // fW2 [64,1024]
                             const float* __restrict__ fb2,   // [1024]
                             int E) {
    __shared__ float As[64][68];   // [k][m], padded for float4 alignment
    __shared__ float Bs[64][64];   // [k][n]

    const float* A = g_h1;
    int m0 = blockIdx.x * 64;
    int n0 = blockIdx.y * 64;
    int tid = threadIdx.x;

    // Load A tile (64 rows x 64 k), transpose into As
    for (int i = tid; i < 1024; i += 256) {
        int r  = i >> 4;
        int c4 = (i & 15) << 2;
        float4 v = *(const float4*)(A + (size_t)(m0 + r) * 64 + c4);
        As[c4 + 0][r] = v.x;
        As[c4 + 1][r] = v.y;
        As[c4 + 2][r] = v.z;
        As[c4 + 3][r] = v.w;
    }
    // Load B tile (64 k x 64 n)
    for (int i = tid; i < 1024; i += 256) {
        int r  = i >> 4;
        int c4 = (i & 15) << 2;
        *(float4*)(&Bs[r][c4]) = *(const float4*)(B + (size_t)r * 1024 + n0 + c4);
    }
    __syncthreads();

    int tm = (tid >> 4) << 2;   // 0..60
    int tn = (tid & 15) << 2;   // 0..60
    float acc[4][4] = {};
#pragma unroll
    for (int k = 0; k < 64; k++) {
        float4 a = *(const float4*)(&As[k][tm]);
        float4 b = *(const float4*)(&Bs[k][tn]);
        float av[4] = {a.x, a.y, a.z, a.w};
        float bv[4] = {b.x, b.y, b.z, b.w};
#pragma unroll
        for (int i = 0; i < 4; i++)
#pragma unroll
            for (int j = 0; j < 4; j++)
                acc[i][j] = fmaf(av[i], bv[j], acc[i][j]);
    }

    float4 bias = *(const float4*)(fb2 + n0 + tn);
#pragma unroll
    for (int i = 0; i < 4; i++) {
        float4 o;
        o.x = acc[i][0] + bias.x;
        o.y = acc[i][1] + bias.y;
        o.z = acc[i][2] + bias.z;
        o.w = acc[i][3] + bias.w;
        *(float4*)(g_weights + (size_t)(m0 + tm + i) * 1024 + n0 + tn) = o;
    }
}

// ---------------------------------------------------------------------------
// init: zero agg + deg
// ---------------------------------------------------------------------------
__global__ void init_kernel(int N) {
    int i = blockIdx.x * blockDim.x + threadIdx.x;
    if (i < N * NC) g_agg[i] = 0.f;
    if (i < N)      g_deg[i] = 0.f;
}

__global__ void count_kernel(const int* __restrict__ dst, int E) {
    int e = blockIdx.x * blockDim.x + threadIdx.x;
    if (e < E) atomicAdd(&g_deg[dst[e]], 1.0f);
}

__global__ void invdeg_kernel(int N) {
    int i = blockIdx.x * blockDim.x + threadIdx.x;
    if (i < N) g_deg[i] = 1.0f / fmaxf(g_deg[i], 1.0f);
}

// ---------------------------------------------------------------------------
// out[:, 0:32] = hx
// ---------------------------------------------------------------------------
__global__ void copy0_kernel(const float* __restrict__ hx, float* __restrict__ out, int N) {
    int i = blockIdx.x * blockDim.x + threadIdx.x;
    if (i >= N * NC) return;
    int n = i >> 5, c = i & 31;
    out[(size_t)n * OUTC + c] = hx[i];
}

// ---------------------------------------------------------------------------
// message + scatter: warp per edge.
// msg[o] = sum_i hx[src,i] * W[e, i*32+o] ; atomicAdd into agg[dst*32+o]
// hx read from out slice (t-1), row stride OUTC.
// ---------------------------------------------------------------------------
__global__ void msg_kernel(const float* __restrict__ out,
                           const int* __restrict__ src,
                           const int* __restrict__ dst,
                           int E, int t) {
    int e    = (blockIdx.x * blockDim.x + threadIdx.x) >> 5;
    int lane = threadIdx.x & 31;
    if (e >= E) return;

    int s = src[e];
    float h = out[(size_t)s * OUTC + (size_t)(t - 1) * NC + lane];
    const float* We = g_weights + (size_t)e * (NC * NC);

    float m = 0.f;
#pragma unroll
    for (int i = 0; i < NC; i++) {
        float hi = __shfl_sync(0xffffffffu, h, i);
        m = fmaf(hi, We[i * NC + lane], m);
    }
    atomicAdd(&g_agg[(size_t)dst[e] * NC + lane], m);
}

// ---------------------------------------------------------------------------
// GRU cell: warp per node, lane = channel. Also zeroes agg for next iter.
// ---------------------------------------------------------------------------
__global__ void gru_kernel(float* __restrict__ out,
                           const float* __restrict__ Wi,
                           const float* __restrict__ Wh,
                           const float* __restrict__ bi,
                           const float* __restrict__ bh,
                           int N, int t) {
    int n    = (blockIdx.x * blockDim.x + threadIdx.x) >> 5;
    int lane = threadIdx.x & 31;
    if (n >= N) return;

    size_t aidx = (size_t)n * NC + lane;
    float x = g_agg[aidx] * g_deg[n];
    g_agg[aidx] = 0.f;   // ready for next iteration's scatter
    float h = out[(size_t)n * OUTC + (size_t)(t - 1) * NC + lane];

    float ir = bi[lane], iz = bi[32 + lane], in_ = bi[64 + lane];
    float hr = bh[lane], hz = bh[32 + lane], hn  = bh[64 + lane];
#pragma unroll
    for (int i = 0; i < NC; i++) {
        float xi = __shfl_sync(0xffffffffu, x, i);
        float hi = __shfl_sync(0xffffffffu, h, i);
        ir = fmaf(xi, Wi[i * 96 + lane],      ir);
        iz = fmaf(xi, Wi[i * 96 + 32 + lane], iz);
        in_ = fmaf(xi, Wi[i * 96 + 64 + lane], in_);
        hr = fmaf(hi, Wh[i * 96 + lane],      hr);
        hz = fmaf(hi, Wh[i * 96 + 32 + lane], hz);
        hn = fmaf(hi, Wh[i * 96 + 64 + lane], hn);
    }
    float r  = 1.0f / (1.0f + expf(-(ir + hr)));
    float z  = 1.0f / (1.0f + expf(-(iz + hz)));
    float nn = tanhf(in_ + r * hn);
    out[(size_t)n * OUTC + (size_t)t * NC + lane] = (1.0f - z) * nn + z * h;
}

// ---------------------------------------------------------------------------
extern "C" void kernel_launch(void* const* d_in, const int* in_sizes, int n_in,
                              void* d_out, int out_size) {
    const float* hx  = (const float*)d_in[0];
    const int*   ei  = (const int*)d_in[1];
    const float* ef  = (const float*)d_in[2];
    const float* fW1 = (const float*)d_in[3];
    const float* fb1 = (const float*)d_in[4];
    const float* fW2 = (const float*)d_in[5];
    const float* fb2 = (const float*)d_in[6];
    const float* Wi  = (const float*)d_in[7];
    const float* Wh  = (const float*)d_in[8];
    const float* bi  = (const float*)d_in[9];
    const float* bh  = (const float*)d_in[10];
    float* out = (float*)d_out;

    const int N = in_sizes[0] / NC;        // 20000
    const int E = in_sizes[1] / 2;         // 200000
    const int* src = ei;
    const int* dst = ei + E;

    // filter net
    h1_kernel<<<(E * 32 + 255) / 256, 256>>>(ef, fW1, fb1, E);
    dim3 ggrid(E / 64, 1024 / 64);
    wgemm_kernel<<<ggrid, 256>>>(fW2, fb2, E);

    // degrees + init
    init_kernel<<<(N * NC + 255) / 256, 256>>>(N);
    count_kernel<<<(E + 255) / 256, 256>>>(dst, E);
    invdeg_kernel<<<(N + 255) / 256, 256>>>(N);

    // out slice 0 = hx
    copy0_kernel<<<(N * NC + 255) / 256, 256>>>(hx, out, N);

    for (int t = 1; t <= NREP; t++) {
        msg_kernel<<<(E * 32 + 255) / 256, 256>>>(out, src, dst, E, t);
        gru_kernel<<<(N * 32 + 255) / 256, 256>>>(out, Wi, Wh, bi, bh, N, t);
    }
}

// round 2
// speedup vs baseline: 1.9757x; 1.9757x over previous
#include <cuda_runtime.h>
#include <cuda_fp16.h>
#include <mma.h>
#include <math.h>

using namespace nvcuda;

// Problem constants (fixed by the dataset)
#define NNODES 20000
#define NEDGES 200000
#define NC     32
#define FDIM   13
#define FHID   64
#define NREP   10
#define OUTC   (NC * (NREP + 1))   // 352

// Scratch (allocation-free rule: __device__ globals)
__device__ __half g_wh[(size_t)NEDGES * NC * NC];   // 400 MB: per-edge [32x32] fp16
__device__ __half g_h1h[(size_t)NEDGES * FHID];     // 25.6 MB
__device__ __half g_fW2h[FHID * NC * NC];           // 128 KB
__device__ float  g_agg[(size_t)NNODES * NC];       // 2.56 MB
__device__ float  g_deg[NNODES];

// ---------------------------------------------------------------------------
// h1 = relu(edge_feats @ fW1 + fb1) -> fp16.  One warp per edge.
// ---------------------------------------------------------------------------
__global__ void h1_kernel(const float* __restrict__ ef,
                          const float* __restrict__ fW1,
                          const float* __restrict__ fb1,
                          int E) {
    int e    = (blockIdx.x * blockDim.x + threadIdx.x) >> 5;
    int lane = threadIdx.x & 31;
    if (e >= E) return;
    float efv = (lane < FDIM) ? ef[(size_t)e * FDIM + lane] : 0.f;
    float a0 = fb1[lane], a1 = fb1[lane + 32];
#pragma unroll
    for (int j = 0; j < FDIM; j++) {
        float x = __shfl_sync(0xffffffffu, efv, j);
        a0 = fmaf(x, fW1[j * FHID + lane],      a0);
        a1 = fmaf(x, fW1[j * FHID + lane + 32], a1);
    }
    g_h1h[(size_t)e * FHID + lane]      = __float2half_rn(fmaxf(a0, 0.f));
    g_h1h[(size_t)e * FHID + lane + 32] = __float2half_rn(fmaxf(a1, 0.f));
}

// fW2 fp32 -> fp16 (once, tiny)
__global__ void cvtB_kernel(const float* __restrict__ fW2) {
    int i = blockIdx.x * blockDim.x + threadIdx.x;
    if (i < FHID * NC * NC) g_fW2h[i] = __float2half_rn(fW2[i]);
}

// ---------------------------------------------------------------------------
// weights = h1 @ fW2 + fb2 via WMMA (fp16 in, fp32 acc), output fp16.
// Block: 256 thr = 8 warps arranged 4(M) x 2(N). Block tile 64x128, K=64.
// ---------------------------------------------------------------------------
#define AS_LD  72
#define BS_LD  136
#define CS_LD  128
#define AS_BYTES (64 * AS_LD * 2)         // 9216
#define BS_BYTES (64 * BS_LD * 2)         // 17408
#define CS_BYTES (64 * CS_LD * 4)         // 32768

__global__ void wgemm_wmma_kernel(const float* __restrict__ fb2) {
    __shared__ __align__(16) unsigned char smem[CS_BYTES];  // union: max(A+B, C)
    __half* As = (__half*)smem;                  // [64][AS_LD]
    __half* Bs = (__half*)(smem + AS_BYTES);     // [64][BS_LD]
    float*  Cs = (float*)smem;                   // [64][CS_LD]

    const int m0 = blockIdx.x * 64;
    const int n0 = blockIdx.y * 128;
    const int tid = threadIdx.x;
    const int wid = tid >> 5;
    const int wm = wid & 3;       // warp row 0..3 -> rows 16*wm
    const int wn = wid >> 2;      // warp col 0..1 -> cols 64*wn

    // Load A tile: 64 rows x 64 halves (128B/row = 8 int4)
#pragma unroll
    for (int i = tid; i < 512; i += 256) {
        int r = i >> 3, s = i & 7;
        *(int4*)(As + r * AS_LD + s * 8) =
            *(const int4*)(g_h1h + (size_t)(m0 + r) * FHID + s * 8);
    }
    // Load B tile: 64 rows x 128 halves (256B/row = 16 int4)
#pragma unroll
    for (int i = tid; i < 1024; i += 256) {
        int r = i >> 4, s = i & 15;
        *(int4*)(Bs + r * BS_LD + s * 8) =
            *(const int4*)(g_fW2h + (size_t)r * 1024 + n0 + s * 8);
    }
    __syncthreads();

    wmma::fragment<wmma::accumulator, 16, 16, 16, float> acc[4];
#pragma unroll
    for (int j = 0; j < 4; j++) wmma::fill_fragment(acc[j], 0.0f);

#pragma unroll
    for (int k = 0; k < 4; k++) {
        wmma::fragment<wmma::matrix_a, 16, 16, 16, __half, wmma::row_major> af;
        wmma::load_matrix_sync(af, As + (wm * 16) * AS_LD + k * 16, AS_LD);
#pragma unroll
        for (int j = 0; j < 4; j++) {
            wmma::fragment<wmma::matrix_b, 16, 16, 16, __half, wmma::row_major> bf;
            wmma::load_matrix_sync(bf, Bs + (k * 16) * BS_LD + wn * 64 + j * 16, BS_LD);
            wmma::mma_sync(acc[j], af, bf, acc[j]);
        }
    }
    __syncthreads();   // done with As/Bs; reuse smem as Cs

#pragma unroll
    for (int j = 0; j < 4; j++)
        wmma::store_matrix_sync(Cs + (wm * 16) * CS_LD + wn * 64 + j * 16,
                                acc[j], CS_LD, wmma::mem_row_major);
    __syncthreads();

    // Add bias, convert to fp16, write out (coalesced half2 stores)
#pragma unroll
    for (int i = tid; i < 64 * 64; i += 256) {
        int r = i >> 6, c2 = i & 63;              // c2: half2 column index
        float v0 = Cs[r * CS_LD + 2 * c2]     + fb2[n0 + 2 * c2];
        float v1 = Cs[r * CS_LD + 2 * c2 + 1] + fb2[n0 + 2 * c2 + 1];
        *(__half2*)(g_wh + (size_t)(m0 + r) * 1024 + n0 + 2 * c2) =
            __floats2half2_rn(v0, v1);
    }
}

// ---------------------------------------------------------------------------
// init / degree
// ---------------------------------------------------------------------------
__global__ void init_kernel(int N) {
    int i = blockIdx.x * blockDim.x + threadIdx.x;
    if (i < N * NC) g_agg[i] = 0.f;
    if (i < N)      g_deg[i] = 0.f;
}

__global__ void count_kernel(const int* __restrict__ dst, int E) {
    int e = blockIdx.x * blockDim.x + threadIdx.x;
    if (e < E) atomicAdd(&g_deg[dst[e]], 1.0f);
}

__global__ void invdeg_kernel(int N) {
    int i = blockIdx.x * blockDim.x + threadIdx.x;
    if (i < N) g_deg[i] = 1.0f / fmaxf(g_deg[i], 1.0f);
}

__global__ void copy0_kernel(const float* __restrict__ hx, float* __restrict__ out, int N) {
    int i = blockIdx.x * blockDim.x + threadIdx.x;
    if (i >= N * NC) return;
    int n = i >> 5, c = i & 31;
    out[(size_t)n * OUTC + c] = hx[i];
}

// ---------------------------------------------------------------------------
// message + scatter: warp per edge, fp16 weights, half2 vectorized.
// Lane l (l<16) covers row 2j outputs (2l,2l+1); lane l>=16 covers row 2j+1.
// ---------------------------------------------------------------------------
__global__ void msg_kernel(const float* __restrict__ out,
                           const int* __restrict__ src,
                           const int* __restrict__ dst,
                           int E, int t) {
    int e    = (blockIdx.x * blockDim.x + threadIdx.x) >> 5;
    int lane = threadIdx.x & 31;
    if (e >= E) return;

    int s = src[e];
    float h = out[(size_t)s * OUTC + (size_t)(t - 1) * NC + lane];
    const __half2* We = (const __half2*)(g_wh + (size_t)e * (NC * NC));
    const int rowsel = lane >> 4;  // 0: even rows, 1: odd rows

    float ax = 0.f, ay = 0.f;
#pragma unroll
    for (int j = 0; j < 16; j++) {
        float hi = __shfl_sync(0xffffffffu, h, 2 * j + rowsel);
        float2 w = __half22float2(We[j * 32 + lane]);
        ax = fmaf(hi, w.x, ax);
        ay = fmaf(hi, w.y, ay);
    }
    // combine even-row and odd-row partials
    ax += __shfl_down_sync(0xffffffffu, ax, 16);
    ay += __shfl_down_sync(0xffffffffu, ay, 16);
    if (lane < 16) {
        int d = dst[e];
        atomicAdd(&g_agg[(size_t)d * NC + 2 * lane],     ax);
        atomicAdd(&g_agg[(size_t)d * NC + 2 * lane + 1], ay);
    }
}

// ---------------------------------------------------------------------------
// GRU cell: warp per node, lane = channel. Also zeroes agg for next iter.
// ---------------------------------------------------------------------------
__global__ void gru_kernel(float* __restrict__ out,
                           const float* __restrict__ Wi,
                           const float* __restrict__ Wh,
                           const float* __restrict__ bi,
                           const float* __restrict__ bh,
                           int N, int t) {
    int n    = (blockIdx.x * blockDim.x + threadIdx.x) >> 5;
    int lane = threadIdx.x & 31;
    if (n >= N) return;

    size_t aidx = (size_t)n * NC + lane;
    float x = g_agg[aidx] * g_deg[n];
    g_agg[aidx] = 0.f;   // ready for next iteration's scatter
    float h = out[(size_t)n * OUTC + (size_t)(t - 1) * NC + lane];

    float ir = bi[lane], iz = bi[32 + lane], in_ = bi[64 + lane];
    float hr = bh[lane], hz = bh[32 + lane], hn  = bh[64 + lane];
#pragma unroll
    for (int i = 0; i < NC; i++) {
        float xi = __shfl_sync(0xffffffffu, x, i);
        float hi = __shfl_sync(0xffffffffu, h, i);
        ir  = fmaf(xi, Wi[i * 96 + lane],      ir);
        iz  = fmaf(xi, Wi[i * 96 + 32 + lane], iz);
        in_ = fmaf(xi, Wi[i * 96 + 64 + lane], in_);
        hr  = fmaf(hi, Wh[i * 96 + lane],      hr);
        hz  = fmaf(hi, Wh[i * 96 + 32 + lane], hz);
        hn  = fmaf(hi, Wh[i * 96 + 64 + lane], hn);
    }
    float r  = 1.0f / (1.0f + expf(-(ir + hr)));
    float z  = 1.0f / (1.0f + expf(-(iz + hz)));
    float nn = tanhf(in_ + r * hn);
    out[(size_t)n * OUTC + (size_t)t * NC + lane] = (1.0f - z) * nn + z * h;
}

// ---------------------------------------------------------------------------
extern "C" void kernel_launch(void* const* d_in, const int* in_sizes, int n_in,
                              void* d_out, int out_size) {
    const float* hx  = (const float*)d_in[0];
    const int*   ei  = (const int*)d_in[1];
    const float* ef  = (const float*)d_in[2];
    const float* fW1 = (const float*)d_in[3];
    const float* fb1 = (const float*)d_in[4];
    const float* fW2 = (const float*)d_in[5];
    const float* fb2 = (const float*)d_in[6];
    const float* Wi  = (const float*)d_in[7];
    const float* Wh  = (const float*)d_in[8];
    const float* bi  = (const float*)d_in[9];
    const float* bh  = (const float*)d_in[10];
    float* out = (float*)d_out;

    const int N = in_sizes[0] / NC;        // 20000
    const int E = in_sizes[1] / 2;         // 200000
    const int* src = ei;
    const int* dst = ei + E;

    // filter net (fp16 path)
    h1_kernel<<<(E * 32 + 255) / 256, 256>>>(ef, fW1, fb1, E);
    cvtB_kernel<<<(FHID * NC * NC + 255) / 256, 256>>>(fW2);
    dim3 ggrid(E / 64, 1024 / 128);
    wgemm_wmma_kernel<<<ggrid, 256>>>(fb2);

    // degrees + init
    init_kernel<<<(N * NC + 255) / 256, 256>>>(N);
    count_kernel<<<(E + 255) / 256, 256>>>(dst, E);
    invdeg_kernel<<<(N + 255) / 256, 256>>>(N);

    // out slice 0 = hx
    copy0_kernel<<<(N * NC + 255) / 256, 256>>>(hx, out, N);

    for (int t = 1; t <= NREP; t++) {
        msg_kernel<<<(E * 32 + 255) / 256, 256>>>(out, src, dst, E, t);
        gru_kernel<<<(N * 32 + 255) / 256, 256>>>(out, Wi, Wh, bi, bh, N, t);
    }
}